// round 4
// baseline (speedup 1.0000x reference)
#include <cuda_runtime.h>
#include <cstdint>

// ---------------------------------------------------------------------------
// HybridBlock: RMS -> merged{k,v,r} GEMM -> RWKV chunked scan -> o-GEMM(+res)
//              -> RMS -> fc-GEMM(leaky^2) -> mlp-GEMM(+res)
// GEMMs: mma.sync.m16n8k8 tf32, cp.async 5-stage pipeline, LDS.128 fragments.
// ---------------------------------------------------------------------------

#define S_LEN 4096
#define B_SZ  4
#define D_DIM 1024
#define H_DIM 4096
#define M_ROWS (B_SZ * S_LEN)      // 16384
#define CH_L  128
#define CH_C  (S_LEN / CH_L)       // 32

// Scratch (device globals: allocation-free per harness rules)
__device__ float g_normed[(size_t)M_ROWS * D_DIM];
__device__ float g_k[(size_t)M_ROWS * D_DIM];
__device__ float g_v[(size_t)M_ROWS * D_DIM];
__device__ float g_r[(size_t)M_ROWS * D_DIM];
__device__ float g_a[(size_t)M_ROWS * D_DIM];
__device__ float g_x1[(size_t)M_ROWS * D_DIM];
__device__ float g_h2[(size_t)M_ROWS * H_DIM];
__device__ float g_carry[CH_C * B_SZ * D_DIM];
__device__ float g_entry[CH_C * B_SZ * D_DIM];
__device__ float g_wcvt[12 * 1024 * 1024];     // tf32-rounded weights

__device__ __forceinline__ uint32_t smem_to_u32(const void* p) {
    uint32_t a;
    asm("{ .reg .u64 t; cvta.to.shared.u64 t, %1; cvt.u32.u64 %0, t; }"
        : "=r"(a) : "l"(p));
    return a;
}

__device__ __forceinline__ uint32_t f2tf32(float f) {
    uint32_t u;
    asm("cvt.rna.tf32.f32 %0, %1;" : "=r"(u) : "f"(f));
    return u;
}
__device__ __forceinline__ float rnd_tf32(float f) {
    return __uint_as_float(f2tf32(f));
}

#define CP_ASYNC16(dst, src) \
    asm volatile("cp.async.cg.shared.global [%0], [%1], 16;" \
                 :: "r"(dst), "l"(src) : "memory")
#define CP_COMMIT() asm volatile("cp.async.commit_group;" ::: "memory")
#define CP_WAIT3()  asm volatile("cp.async.wait_group 3;" ::: "memory")

#define LDS128(r0, r1, r2, r3, addr) \
    asm volatile("ld.shared.v4.b32 {%0,%1,%2,%3}, [%4];" \
                 : "=r"(r0), "=r"(r1), "=r"(r2), "=r"(r3) : "r"(addr))

#define MMA_TF32(d, a0, a1, a2, a3, b0, b1) \
    asm volatile( \
        "mma.sync.aligned.m16n8k8.row.col.f32.tf32.tf32.f32 " \
        "{%0,%1,%2,%3}, {%4,%5,%6,%7}, {%8,%9}, {%0,%1,%2,%3};\n" \
        : "+f"((d)[0]), "+f"((d)[1]), "+f"((d)[2]), "+f"((d)[3]) \
        : "r"(a0), "r"(a1), "r"(a2), "r"(a3), "r"(b0), "r"(b1))

// ---------------------------------------------------------------------------
// Fused weight pre-round to tf32 (rna): all 6 weights, one launch.
// Layout in g_wcvt: [Wk 1M][Wv 1M][Wr 1M][Wo 1M][Wfc 4M][Wmlp 4M]
// ---------------------------------------------------------------------------
__global__ void cvt_all_kernel(const float* __restrict__ Wk, const float* __restrict__ Wv,
                               const float* __restrict__ Wr, const float* __restrict__ Wo,
                               const float* __restrict__ Wfc, const float* __restrict__ Wmlp) {
    const int M1 = 1024 * 1024 / 4;     // float4 count per 1M-float weight
    const size_t i = (size_t)blockIdx.x * 256 + threadIdx.x;  // 0 .. 3M-1 float4
    const float* src;
    size_t li;
    if (i < 4 * M1) { src = (i < M1) ? Wk : (i < 2 * M1) ? Wv : (i < 3 * M1) ? Wr : Wo;
                      li = i & (M1 - 1); }
    else if (i < 8 * M1) { src = Wfc;  li = i - 4 * M1; }
    else                 { src = Wmlp; li = i - 8 * M1; }
    const float4 v = reinterpret_cast<const float4*>(src)[li];
    float4 o;
    o.x = rnd_tf32(v.x); o.y = rnd_tf32(v.y);
    o.z = rnd_tf32(v.z); o.w = rnd_tf32(v.w);
    reinterpret_cast<float4*>(g_wcvt)[i] = o;
}

// ---------------------------------------------------------------------------
// RMS norm: warp per row, no block sync. Output pre-rounded to tf32.
// ---------------------------------------------------------------------------
__global__ void rms_kernel(const float* __restrict__ x, float* __restrict__ out) {
    const int w = threadIdx.x >> 5, lid = threadIdx.x & 31;
    const int row = blockIdx.x * 8 + w;
    const float4* xr = reinterpret_cast<const float4*>(x + (size_t)row * D_DIM);
    float4 va[8];
    float ss = 0.f;
    #pragma unroll
    for (int i = 0; i < 8; i++) {
        va[i] = xr[lid + 32 * i];
        ss += va[i].x * va[i].x + va[i].y * va[i].y + va[i].z * va[i].z + va[i].w * va[i].w;
    }
    #pragma unroll
    for (int o = 16; o > 0; o >>= 1) ss += __shfl_xor_sync(0xffffffffu, ss, o);
    const float inv = rsqrtf(ss * (1.0f / (float)D_DIM) + 1e-6f);
    float4* orow = reinterpret_cast<float4*>(out + (size_t)row * D_DIM);
    #pragma unroll
    for (int i = 0; i < 8; i++) {
        float4 o4;
        o4.x = rnd_tf32(va[i].x * inv); o4.y = rnd_tf32(va[i].y * inv);
        o4.z = rnd_tf32(va[i].z * inv); o4.w = rnd_tf32(va[i].w * inv);
        orow[lid + 32 * i] = o4;
    }
}

// ---------------------------------------------------------------------------
// RWKV chunked scan (exact factorization, per-channel constant decay)
// ---------------------------------------------------------------------------
__global__ void scan_carry(const float* __restrict__ k, const float* __restrict__ v,
                           const float* __restrict__ td) {
    const int d = blockIdx.x * 256 + threadIdx.x;
    const int c = blockIdx.y, b = blockIdx.z;
    const float ew = expf(-expf(td[d]));
    size_t base = ((size_t)b * S_LEN + (size_t)c * CH_L) * D_DIM + d;
    float carry = 0.f;
    #pragma unroll 4
    for (int i = 0; i < CH_L; i++) {
        const float kv = k[base] * v[base];
        carry = ew * carry + kv;
        base += D_DIM;
    }
    g_carry[((size_t)c * B_SZ + b) * D_DIM + d] = carry;
}

__global__ void scan_combine(const float* __restrict__ td) {
    const int d = blockIdx.x * 256 + threadIdx.x;
    const int b = blockIdx.y;
    const float ewL = expf(-(float)CH_L * expf(td[d]));
    float s = 0.f;
    #pragma unroll
    for (int c = 0; c < CH_C; c++) {
        const size_t idx = ((size_t)c * B_SZ + b) * D_DIM + d;
        g_entry[idx] = s;
        s = ewL * s + g_carry[idx];
    }
}

__global__ void scan_apply(const float* __restrict__ k, const float* __restrict__ v,
                           const float* __restrict__ r,
                           const float* __restrict__ td, const float* __restrict__ tfirst) {
    const int d = blockIdx.x * 256 + threadIdx.x;
    const int c = blockIdx.y, b = blockIdx.z;
    const float ew = expf(-expf(td[d]));
    const float eu = expf(tfirst[d]);
    float s = g_entry[((size_t)c * B_SZ + b) * D_DIM + d];
    size_t base = ((size_t)b * S_LEN + (size_t)c * CH_L) * D_DIM + d;
    #pragma unroll 4
    for (int i = 0; i < CH_L; i++) {
        const float kv = k[base] * v[base];
        const float wkv = s + eu * kv;
        g_a[base] = rnd_tf32(r[base] * wkv);   // GEMM A operand: pre-round
        s = ew * s + kv;
        base += D_DIM;
    }
}

// ---------------------------------------------------------------------------
// tf32 mma.sync GEMM: C[M,N] = A[M,K] @ B[N,K]^T, inputs pre-rounded to tf32.
// Block 128x128x16, 256 threads (8 warps 2x4), warp tile 64x32.
// cp.async 5-stage ring (80KB smem), 2 CTAs/SM.
// EPI: 0=none 1=sigmoid 2=res+scale*acc 3=(leaky0.5)^2 4=merged-kvr
// For EPI 4: C=k dest, res=v dest, scale=r dest; seg = bn>>3.
// ---------------------------------------------------------------------------
#define NST 5
#define STAGE_BYTES 16384    // A 8KB + B 8KB
#define SMEM_TOTAL (NST * STAGE_BYTES)

template <int EPI>
__global__ void __launch_bounds__(256, 2) gemm_mma(
    const float* __restrict__ A, const float* __restrict__ Bw,
    float* __restrict__ C, int K, int N,
    const float* __restrict__ res, const float* __restrict__ scale)
{
    extern __shared__ char smem[];
    const uint32_t sb = smem_to_u32(smem);
    const int tid = threadIdx.x;
    const int bn = blockIdx.x, bm = blockIdx.y;
    const int warp = tid >> 5, lane = tid & 31;
    const int wm = warp >> 2, wn = warp & 3;      // 2x4 warp grid
    const int gid = lane >> 2, tig = lane & 3;

    const float* Ab = A + (size_t)bm * 128 * K;
    const float* Bb = Bw + (size_t)bn * 128 * K;

    // cp.async mapping: stage = 512 A-chunks + 512 B-chunks (16B each).
    const int i0 = tid, i1 = 256 + tid;
    const float* gA0 = Ab + (size_t)(i0 >> 2) * K + (i0 & 3) * 4;
    const float* gA1 = Ab + (size_t)(i1 >> 2) * K + (i1 & 3) * 4;
    const float* gB0 = Bb + (size_t)(i0 >> 2) * K + (i0 & 3) * 4;
    const float* gB1 = Bb + (size_t)(i1 >> 2) * K + (i1 & 3) * 4;
    const uint32_t dA0 = sb + i0 * 16, dA1 = sb + i1 * 16;
    const uint32_t dB0 = sb + 8192 + i0 * 16, dB1 = sb + 8192 + i1 * 16;

    float acc[4][4][4];
    #pragma unroll
    for (int i = 0; i < 4; i++)
        #pragma unroll
        for (int j = 0; j < 4; j++)
            #pragma unroll
            for (int l = 0; l < 4; l++) acc[i][j][l] = 0.f;

    const int KT = K >> 4;

    // prologue: stages 0..3
    #pragma unroll
    for (int s = 0; s < NST - 1; s++) {
        const uint32_t so = s * STAGE_BYTES;
        const int ko = s * 16;
        CP_ASYNC16(dA0 + so, gA0 + ko);
        CP_ASYNC16(dA1 + so, gA1 + ko);
        CP_ASYNC16(dB0 + so, gB0 + ko);
        CP_ASYNC16(dB1 + so, gB1 + ko);
        CP_COMMIT();
    }

    const uint32_t a_base = sb + (uint32_t)(wm * 64 + gid) * 64 + tig * 16;
    const uint32_t b_base = sb + 8192 + (uint32_t)(wn * 32 + gid) * 64 + tig * 16;

    int s_cur = 0, s_nxt = NST - 1;
    for (int kt = 0; kt < KT; kt++) {
        CP_WAIT3();
        __syncthreads();

        const uint32_t so = (uint32_t)s_cur * STAGE_BYTES;
        uint32_t bf[4][4];
        #pragma unroll
        for (int ni = 0; ni < 4; ni++)
            LDS128(bf[ni][0], bf[ni][1], bf[ni][2], bf[ni][3], b_base + so + ni * 512);

        #pragma unroll
        for (int mi = 0; mi < 4; mi++) {
            uint32_t lo0, lo1, lo2, lo3, hi0, hi1, hi2, hi3;
            LDS128(lo0, lo1, lo2, lo3, a_base + so + mi * 1024);
            LDS128(hi0, hi1, hi2, hi3, a_base + so + mi * 1024 + 512);
            #pragma unroll
            for (int ni = 0; ni < 4; ni++) {
                MMA_TF32(acc[mi][ni], lo0, hi0, lo1, hi1, bf[ni][0], bf[ni][1]);
                MMA_TF32(acc[mi][ni], lo2, hi2, lo3, hi3, bf[ni][2], bf[ni][3]);
            }
        }

        const int kn = kt + NST - 1;
        if (kn < KT) {
            const uint32_t sn = (uint32_t)s_nxt * STAGE_BYTES;
            const int ko = kn * 16;
            CP_ASYNC16(dA0 + sn, gA0 + ko);
            CP_ASYNC16(dA1 + sn, gA1 + ko);
            CP_ASYNC16(dB0 + sn, gB0 + ko);
            CP_ASYNC16(dB1 + sn, gB1 + ko);
        }
        CP_COMMIT();
        if (++s_cur == NST) s_cur = 0;
        if (++s_nxt == NST) s_nxt = 0;
    }

    // epilogue (C fragment: c0,c1 @ row gid cols 2tig,2tig+1; c2,c3 @ row gid+8)
    float* Cd = C;
    int seg = 0, Nout = N, col_base = bn * 128;
    if (EPI == 4) {
        seg = bn >> 3;
        Cd = (seg == 0) ? C : (seg == 1) ? (float*)res : (float*)scale;
        Nout = D_DIM;
        col_base = (bn & 7) * 128;
    }
    const int row0 = bm * 128 + wm * 64 + gid;
    const int col0 = col_base + wn * 32 + 2 * tig;
    #pragma unroll
    for (int mi = 0; mi < 4; mi++) {
        #pragma unroll
        for (int ni = 0; ni < 4; ni++) {
            const int gc = col0 + ni * 8;
            #pragma unroll
            for (int h = 0; h < 2; h++) {
                const int gr = row0 + mi * 16 + h * 8;
                float v0 = acc[mi][ni][2 * h + 0];
                float v1 = acc[mi][ni][2 * h + 1];
                if (EPI == 1) {
                    v0 = 1.f / (1.f + expf(-v0));
                    v1 = 1.f / (1.f + expf(-v1));
                } else if (EPI == 2) {
                    const float2 rr = *reinterpret_cast<const float2*>(res + (size_t)gr * N + gc);
                    const float2 sc = *reinterpret_cast<const float2*>(scale + gc);
                    v0 = rr.x + sc.x * v0;
                    v1 = rr.y + sc.y * v1;
                } else if (EPI == 3) {
                    const float t0 = v0 > 0.f ? v0 : 0.5f * v0;
                    const float t1 = v1 > 0.f ? v1 : 0.5f * v1;
                    v0 = rnd_tf32(t0 * t0);    // next GEMM's A operand
                    v1 = rnd_tf32(t1 * t1);
                } else if (EPI == 4) {
                    if (seg == 2) {            // r: sigmoid
                        v0 = 1.f / (1.f + expf(-v0));
                        v1 = 1.f / (1.f + expf(-v1));
                    }
                }
                *reinterpret_cast<float2*>(Cd + (size_t)gr * Nout + gc) = make_float2(v0, v1);
            }
        }
    }
}

// ---------------------------------------------------------------------------
// Launch
// ---------------------------------------------------------------------------
extern "C" void kernel_launch(void* const* d_in, const int* in_sizes, int n_in,
                              void* d_out, int out_size) {
    const float* x     = (const float*)d_in[0];
    const float* Wk    = (const float*)d_in[1];
    const float* Wv    = (const float*)d_in[2];
    const float* Wr    = (const float*)d_in[3];
    const float* Wo    = (const float*)d_in[4];
    const float* td    = (const float*)d_in[5];
    const float* tfst  = (const float*)d_in[6];
    const float* mscl  = (const float*)d_in[7];
    const float* Wfc   = (const float*)d_in[8];
    const float* Wmlp  = (const float*)d_in[9];
    const float* pscl  = (const float*)d_in[10];
    float* out = (float*)d_out;

    float *p_normed, *p_k, *p_v, *p_r, *p_a, *p_x1, *p_h2, *p_w;
    cudaGetSymbolAddress((void**)&p_normed, g_normed);
    cudaGetSymbolAddress((void**)&p_k, g_k);
    cudaGetSymbolAddress((void**)&p_v, g_v);
    cudaGetSymbolAddress((void**)&p_r, g_r);
    cudaGetSymbolAddress((void**)&p_a, g_a);
    cudaGetSymbolAddress((void**)&p_x1, g_x1);
    cudaGetSymbolAddress((void**)&p_h2, g_h2);
    cudaGetSymbolAddress((void**)&p_w, g_wcvt);

    float* cWkvr = p_w;                                  // [3072,1024] contiguous
    float* cWo   = p_w + (size_t)3 * 1024 * 1024;
    float* cWfc  = p_w + (size_t)4 * 1024 * 1024;
    float* cWmlp = p_w + (size_t)8 * 1024 * 1024;

    cudaFuncSetAttribute(gemm_mma<2>, cudaFuncAttributeMaxDynamicSharedMemorySize, SMEM_TOTAL);
    cudaFuncSetAttribute(gemm_mma<3>, cudaFuncAttributeMaxDynamicSharedMemorySize, SMEM_TOTAL);
    cudaFuncSetAttribute(gemm_mma<4>, cudaFuncAttributeMaxDynamicSharedMemorySize, SMEM_TOTAL);

    const dim3 gemmD(D_DIM / 128, M_ROWS / 128);    // (8, 128)
    const dim3 gemmKVR(3 * D_DIM / 128, M_ROWS / 128);  // (24, 128)
    const dim3 gemmH(H_DIM / 128, M_ROWS / 128);    // (32, 128)

    // 0) pre-round all weights to tf32 (one launch)
    cvt_all_kernel<<<(12 * 1024 * 1024 / 4) / 256, 256>>>(Wk, Wv, Wr, Wo, Wfc, Wmlp);
    // 1) RMS(x)
    rms_kernel<<<M_ROWS / 8, 256>>>(x, p_normed);
    // 2) merged k|v|r GEMM
    gemm_mma<4><<<gemmKVR, 256, SMEM_TOTAL>>>(p_normed, cWkvr, p_k, D_DIM, 3 * D_DIM, p_v, p_r);
    // 3) chunked RWKV scan, fuse r*wkv into g_a
    scan_carry<<<dim3(D_DIM / 256, CH_C, B_SZ), 256>>>(p_k, p_v, td);
    scan_combine<<<dim3(D_DIM / 256, B_SZ), 256>>>(td);
    scan_apply<<<dim3(D_DIM / 256, CH_C, B_SZ), 256>>>(p_k, p_v, p_r, td, tfst);
    // 4) o-GEMM + residual -> x1
    gemm_mma<2><<<gemmD, 256, SMEM_TOTAL>>>(p_a, cWo, p_x1, D_DIM, D_DIM, x, mscl);
    // 5) RMS(x1)
    rms_kernel<<<M_ROWS / 8, 256>>>(p_x1, p_normed);
    // 6) fc-GEMM with leaky(0.5)^2 epilogue -> h2
    gemm_mma<3><<<gemmH, 256, SMEM_TOTAL>>>(p_normed, cWfc, p_h2, D_DIM, H_DIM, nullptr, nullptr);
    // 7) mlp-GEMM + residual -> out
    gemm_mma<2><<<gemmD, 256, SMEM_TOTAL>>>(p_h2, cWmlp, out, H_DIM, D_DIM, p_x1, pscl);
}

// round 5
// speedup vs baseline: 1.7847x; 1.7847x over previous
#include <cuda_runtime.h>
#include <cuda_fp16.h>
#include <cstdint>

// ---------------------------------------------------------------------------
// HybridBlock: RMS -> merged{k,v,r} GEMM -> RWKV chunked scan -> o-GEMM(+res)
//              -> RMS -> fc-GEMM(leaky^2) -> mlp-GEMM(+res)
// GEMMs: mma.sync.m16n8k16 fp16 (fp32 accum), cp.async 6-stage pipeline.
// fp16 mantissa == tf32 mantissa (10 bits) => same rounding error, 2x rate.
// ---------------------------------------------------------------------------

#define S_LEN 4096
#define B_SZ  4
#define D_DIM 1024
#define H_DIM 4096
#define M_ROWS (B_SZ * S_LEN)      // 16384
#define CH_L  128
#define CH_C  (S_LEN / CH_L)       // 32

// Scratch (device globals: allocation-free per harness rules)
__device__ __half g_normed[(size_t)M_ROWS * D_DIM];
__device__ float  g_k[(size_t)M_ROWS * D_DIM];
__device__ float  g_v[(size_t)M_ROWS * D_DIM];
__device__ float  g_r[(size_t)M_ROWS * D_DIM];
__device__ __half g_a[(size_t)M_ROWS * D_DIM];
__device__ float  g_x1[(size_t)M_ROWS * D_DIM];
__device__ __half g_h2[(size_t)M_ROWS * H_DIM];
__device__ float  g_carry[CH_C * B_SZ * D_DIM];
__device__ float  g_entry[CH_C * B_SZ * D_DIM];
__device__ __half g_wh[(size_t)12 * 1024 * 1024];   // fp16 weights

__device__ __forceinline__ uint32_t smem_to_u32(const void* p) {
    uint32_t a;
    asm("{ .reg .u64 t; cvta.to.shared.u64 t, %1; cvt.u32.u64 %0, t; }"
        : "=r"(a) : "l"(p));
    return a;
}

#define CP_ASYNC16(dst, src) \
    asm volatile("cp.async.cg.shared.global [%0], [%1], 16;" \
                 :: "r"(dst), "l"(src) : "memory")
#define CP_COMMIT() asm volatile("cp.async.commit_group;" ::: "memory")
#define CP_WAIT4()  asm volatile("cp.async.wait_group 4;" ::: "memory")

#define LDS128(r0, r1, r2, r3, addr) \
    asm volatile("ld.shared.v4.b32 {%0,%1,%2,%3}, [%4];" \
                 : "=r"(r0), "=r"(r1), "=r"(r2), "=r"(r3) : "r"(addr))

#define MMA_F16(d, a0, a1, a2, a3, b0, b1) \
    asm volatile( \
        "mma.sync.aligned.m16n8k16.row.col.f32.f16.f16.f32 " \
        "{%0,%1,%2,%3}, {%4,%5,%6,%7}, {%8,%9}, {%0,%1,%2,%3};\n" \
        : "+f"((d)[0]), "+f"((d)[1]), "+f"((d)[2]), "+f"((d)[3]) \
        : "r"(a0), "r"(a1), "r"(a2), "r"(a3), "r"(b0), "r"(b1))

// ---------------------------------------------------------------------------
// Weight convert fp32 -> fp16, all 6 weights in one launch.
// g_wh layout: [Wk 1M][Wv 1M][Wr 1M][Wo 1M][Wfc 4M][Wmlp 4M] (floats count)
// ---------------------------------------------------------------------------
__global__ void cvt_all_kernel(const float* __restrict__ Wk, const float* __restrict__ Wv,
                               const float* __restrict__ Wr, const float* __restrict__ Wo,
                               const float* __restrict__ Wfc, const float* __restrict__ Wmlp) {
    const int M1 = 1024 * 1024 / 4;
    const size_t i = (size_t)blockIdx.x * 256 + threadIdx.x;  // float4 index
    const float* src;
    size_t li;
    if (i < 4 * M1) { src = (i < M1) ? Wk : (i < 2 * M1) ? Wv : (i < 3 * M1) ? Wr : Wo;
                      li = i & (M1 - 1); }
    else if (i < 8 * M1) { src = Wfc;  li = i - 4 * M1; }
    else                 { src = Wmlp; li = i - 8 * M1; }
    const float4 v = reinterpret_cast<const float4*>(src)[li];
    const __half2 h0 = __floats2half2_rn(v.x, v.y);
    const __half2 h1 = __floats2half2_rn(v.z, v.w);
    uint2 u;
    u.x = *reinterpret_cast<const uint32_t*>(&h0);
    u.y = *reinterpret_cast<const uint32_t*>(&h1);
    reinterpret_cast<uint2*>(g_wh)[i] = u;
}

// ---------------------------------------------------------------------------
// RMS norm: warp per row, output fp16.
// ---------------------------------------------------------------------------
__global__ void rms_kernel(const float* __restrict__ x, __half* __restrict__ out) {
    const int w = threadIdx.x >> 5, lid = threadIdx.x & 31;
    const int row = blockIdx.x * 8 + w;
    const float4* xr = reinterpret_cast<const float4*>(x + (size_t)row * D_DIM);
    float4 va[8];
    float ss = 0.f;
    #pragma unroll
    for (int i = 0; i < 8; i++) {
        va[i] = xr[lid + 32 * i];
        ss += va[i].x * va[i].x + va[i].y * va[i].y + va[i].z * va[i].z + va[i].w * va[i].w;
    }
    #pragma unroll
    for (int o = 16; o > 0; o >>= 1) ss += __shfl_xor_sync(0xffffffffu, ss, o);
    const float inv = rsqrtf(ss * (1.0f / (float)D_DIM) + 1e-6f);
    uint2* orow = reinterpret_cast<uint2*>(out + (size_t)row * D_DIM);
    #pragma unroll
    for (int i = 0; i < 8; i++) {
        const __half2 h0 = __floats2half2_rn(va[i].x * inv, va[i].y * inv);
        const __half2 h1 = __floats2half2_rn(va[i].z * inv, va[i].w * inv);
        uint2 u;
        u.x = *reinterpret_cast<const uint32_t*>(&h0);
        u.y = *reinterpret_cast<const uint32_t*>(&h1);
        orow[lid + 32 * i] = u;
    }
}

// ---------------------------------------------------------------------------
// RWKV chunked scan (fp32 exact factorization)
// ---------------------------------------------------------------------------
__global__ void scan_carry(const float* __restrict__ k, const float* __restrict__ v,
                           const float* __restrict__ td) {
    const int d = blockIdx.x * 256 + threadIdx.x;
    const int c = blockIdx.y, b = blockIdx.z;
    const float ew = expf(-expf(td[d]));
    size_t base = ((size_t)b * S_LEN + (size_t)c * CH_L) * D_DIM + d;
    float carry = 0.f;
    #pragma unroll 4
    for (int i = 0; i < CH_L; i++) {
        const float kv = k[base] * v[base];
        carry = ew * carry + kv;
        base += D_DIM;
    }
    g_carry[((size_t)c * B_SZ + b) * D_DIM + d] = carry;
}

__global__ void scan_combine(const float* __restrict__ td) {
    const int d = blockIdx.x * 256 + threadIdx.x;
    const int b = blockIdx.y;
    const float ewL = expf(-(float)CH_L * expf(td[d]));
    float s = 0.f;
    #pragma unroll
    for (int c = 0; c < CH_C; c++) {
        const size_t idx = ((size_t)c * B_SZ + b) * D_DIM + d;
        g_entry[idx] = s;
        s = ewL * s + g_carry[idx];
    }
}

__global__ void scan_apply(const float* __restrict__ k, const float* __restrict__ v,
                           const float* __restrict__ r,
                           const float* __restrict__ td, const float* __restrict__ tfirst) {
    const int d = blockIdx.x * 256 + threadIdx.x;
    const int c = blockIdx.y, b = blockIdx.z;
    const float ew = expf(-expf(td[d]));
    const float eu = expf(tfirst[d]);
    float s = g_entry[((size_t)c * B_SZ + b) * D_DIM + d];
    size_t base = ((size_t)b * S_LEN + (size_t)c * CH_L) * D_DIM + d;
    #pragma unroll 4
    for (int i = 0; i < CH_L; i++) {
        const float kv = k[base] * v[base];
        const float wkv = s + eu * kv;
        g_a[base] = __float2half_rn(r[base] * wkv);   // next GEMM A operand
        s = ew * s + kv;
        base += D_DIM;
    }
}

// ---------------------------------------------------------------------------
// fp16 mma.sync GEMM: C[M,N] = A[M,K] @ B[N,K]^T (A,B fp16, fp32 accum).
// Block 128x128xK32, 256 threads (8 warps 2x4), warp tile 64x32.
// smem rows: 32 halfs (64B) per row per K-tile; LDS.128 = 8 halfs covers
// two k16 mma steps via a shared logical-k relabeling (exact).
// cp.async 6-stage ring (96KB), 2 CTAs/SM.
// EPI: 2=res+scale*acc (f32 out) 3=(leaky0.5)^2 (fp16 out) 4=merged-kvr (f32)
// ---------------------------------------------------------------------------
#define NST 6
#define STAGE_BYTES 16384    // A 8KB + B 8KB
#define SMEM_TOTAL (NST * STAGE_BYTES)

template <int EPI>
__global__ void __launch_bounds__(256, 2) gemm_h(
    const __half* __restrict__ A, const __half* __restrict__ Bw,
    void* __restrict__ Cout, int K, int N,
    const float* __restrict__ res, const float* __restrict__ scale)
{
    extern __shared__ char smem[];
    const uint32_t sb = smem_to_u32(smem);
    const int tid = threadIdx.x;
    const int bn = blockIdx.x, bm = blockIdx.y;
    const int warp = tid >> 5, lane = tid & 31;
    const int wm = warp >> 2, wn = warp & 3;      // 2x4 warp grid
    const int gid = lane >> 2, tig = lane & 3;

    const __half* Ab = A + (size_t)bm * 128 * K;
    const __half* Bb = Bw + (size_t)bn * 128 * K;

    // cp.async: stage = 512 A-chunks + 512 B-chunks, 16B (8 halfs) each.
    // chunk i: row i>>2, k-offset (i&3)*8 halfs within 32-half tile.
    const int i0 = tid, i1 = 256 + tid;
    const __half* gA0 = Ab + (size_t)(i0 >> 2) * K + (i0 & 3) * 8;
    const __half* gA1 = Ab + (size_t)(i1 >> 2) * K + (i1 & 3) * 8;
    const __half* gB0 = Bb + (size_t)(i0 >> 2) * K + (i0 & 3) * 8;
    const __half* gB1 = Bb + (size_t)(i1 >> 2) * K + (i1 & 3) * 8;
    const uint32_t dA0 = sb + i0 * 16, dA1 = sb + i1 * 16;
    const uint32_t dB0 = sb + 8192 + i0 * 16, dB1 = sb + 8192 + i1 * 16;

    float acc[4][4][4];
    #pragma unroll
    for (int i = 0; i < 4; i++)
        #pragma unroll
        for (int j = 0; j < 4; j++)
            #pragma unroll
            for (int l = 0; l < 4; l++) acc[i][j][l] = 0.f;

    const int KT = K >> 5;     // 32 halfs per tile

    // prologue: stages 0..4
    #pragma unroll
    for (int s = 0; s < NST - 1; s++) {
        const uint32_t so = s * STAGE_BYTES;
        const int ko = s * 32;
        CP_ASYNC16(dA0 + so, gA0 + ko);
        CP_ASYNC16(dA1 + so, gA1 + ko);
        CP_ASYNC16(dB0 + so, gB0 + ko);
        CP_ASYNC16(dB1 + so, gB1 + ko);
        CP_COMMIT();
    }

    const uint32_t a_base = sb + (uint32_t)(wm * 64 + gid) * 64 + tig * 16;
    const uint32_t b_base = sb + 8192 + (uint32_t)(wn * 32 + gid) * 64 + tig * 16;

    int s_cur = 0, s_nxt = NST - 1;
    for (int kt = 0; kt < KT; kt++) {
        CP_WAIT4();
        __syncthreads();

        // prefetch stage s_nxt right away (its consumers finished last iter)
        const int kn = kt + NST - 1;
        if (kn < KT) {
            const uint32_t sn = (uint32_t)s_nxt * STAGE_BYTES;
            const int ko = kn * 32;
            CP_ASYNC16(dA0 + sn, gA0 + ko);
            CP_ASYNC16(dA1 + sn, gA1 + ko);
            CP_ASYNC16(dB0 + sn, gB0 + ko);
            CP_ASYNC16(dB1 + sn, gB1 + ko);
        }
        CP_COMMIT();

        const uint32_t so = (uint32_t)s_cur * STAGE_BYTES;
        uint32_t bf[4][4];
        #pragma unroll
        for (int ni = 0; ni < 4; ni++)
            LDS128(bf[ni][0], bf[ni][1], bf[ni][2], bf[ni][3], b_base + so + ni * 512);

        #pragma unroll
        for (int mi = 0; mi < 4; mi++) {
            uint32_t lo0, lo1, lo2, lo3, hi0, hi1, hi2, hi3;
            LDS128(lo0, lo1, lo2, lo3, a_base + so + mi * 1024);
            LDS128(hi0, hi1, hi2, hi3, a_base + so + mi * 1024 + 512);
            #pragma unroll
            for (int ni = 0; ni < 4; ni++) {
                MMA_F16(acc[mi][ni], lo0, hi0, lo1, hi1, bf[ni][0], bf[ni][1]);  // k-step 0
                MMA_F16(acc[mi][ni], lo2, hi2, lo3, hi3, bf[ni][2], bf[ni][3]);  // k-step 1
            }
        }

        if (++s_cur == NST) s_cur = 0;
        if (++s_nxt == NST) s_nxt = 0;
    }

    // epilogue
    float* Cf = (float*)Cout;
    __half* Ch = (__half*)Cout;
    int seg = 0, Nout = N, col_base = bn * 128;
    if (EPI == 4) {
        seg = bn >> 3;
        Cf = (seg == 0) ? (float*)Cout : (seg == 1) ? (float*)res : (float*)scale;
        Nout = D_DIM;
        col_base = (bn & 7) * 128;
    }
    const int row0 = bm * 128 + wm * 64 + gid;
    const int col0 = col_base + wn * 32 + 2 * tig;
    #pragma unroll
    for (int mi = 0; mi < 4; mi++) {
        #pragma unroll
        for (int ni = 0; ni < 4; ni++) {
            const int gc = col0 + ni * 8;
            #pragma unroll
            for (int h = 0; h < 2; h++) {
                const int gr = row0 + mi * 16 + h * 8;
                float v0 = acc[mi][ni][2 * h + 0];
                float v1 = acc[mi][ni][2 * h + 1];
                if (EPI == 2) {
                    const float2 rr = *reinterpret_cast<const float2*>(res + (size_t)gr * N + gc);
                    const float2 sc = *reinterpret_cast<const float2*>(scale + gc);
                    *reinterpret_cast<float2*>(Cf + (size_t)gr * N + gc) =
                        make_float2(rr.x + sc.x * v0, rr.y + sc.y * v1);
                } else if (EPI == 3) {
                    const float t0 = v0 > 0.f ? v0 : 0.5f * v0;
                    const float t1 = v1 > 0.f ? v1 : 0.5f * v1;
                    const __half2 hv = __floats2half2_rn(t0 * t0, t1 * t1);
                    *reinterpret_cast<__half2*>(Ch + (size_t)gr * N + gc) = hv;
                } else if (EPI == 4) {
                    if (seg == 2) {
                        v0 = 1.f / (1.f + expf(-v0));
                        v1 = 1.f / (1.f + expf(-v1));
                    }
                    *reinterpret_cast<float2*>(Cf + (size_t)gr * Nout + gc) =
                        make_float2(v0, v1);
                }
            }
        }
    }
}

// ---------------------------------------------------------------------------
// Launch
// ---------------------------------------------------------------------------
extern "C" void kernel_launch(void* const* d_in, const int* in_sizes, int n_in,
                              void* d_out, int out_size) {
    const float* x     = (const float*)d_in[0];
    const float* Wk    = (const float*)d_in[1];
    const float* Wv    = (const float*)d_in[2];
    const float* Wr    = (const float*)d_in[3];
    const float* Wo    = (const float*)d_in[4];
    const float* td    = (const float*)d_in[5];
    const float* tfst  = (const float*)d_in[6];
    const float* mscl  = (const float*)d_in[7];
    const float* Wfc   = (const float*)d_in[8];
    const float* Wmlp  = (const float*)d_in[9];
    const float* pscl  = (const float*)d_in[10];
    float* out = (float*)d_out;

    float *p_k, *p_v, *p_r, *p_x1;
    __half *p_normed, *p_a, *p_h2, *p_w;
    cudaGetSymbolAddress((void**)&p_normed, g_normed);
    cudaGetSymbolAddress((void**)&p_k, g_k);
    cudaGetSymbolAddress((void**)&p_v, g_v);
    cudaGetSymbolAddress((void**)&p_r, g_r);
    cudaGetSymbolAddress((void**)&p_a, g_a);
    cudaGetSymbolAddress((void**)&p_x1, g_x1);
    cudaGetSymbolAddress((void**)&p_h2, g_h2);
    cudaGetSymbolAddress((void**)&p_w, g_wh);

    __half* cWkvr = p_w;                                  // [3072,1024]
    __half* cWo   = p_w + (size_t)3 * 1024 * 1024;
    __half* cWfc  = p_w + (size_t)4 * 1024 * 1024;
    __half* cWmlp = p_w + (size_t)8 * 1024 * 1024;

    cudaFuncSetAttribute(gemm_h<2>, cudaFuncAttributeMaxDynamicSharedMemorySize, SMEM_TOTAL);
    cudaFuncSetAttribute(gemm_h<3>, cudaFuncAttributeMaxDynamicSharedMemorySize, SMEM_TOTAL);
    cudaFuncSetAttribute(gemm_h<4>, cudaFuncAttributeMaxDynamicSharedMemorySize, SMEM_TOTAL);

    const dim3 gemmD(D_DIM / 128, M_ROWS / 128);        // (8, 128)
    const dim3 gemmKVR(3 * D_DIM / 128, M_ROWS / 128);  // (24, 128)
    const dim3 gemmH(H_DIM / 128, M_ROWS / 128);        // (32, 128)

    // 0) weights -> fp16 (one launch)
    cvt_all_kernel<<<(12 * 1024 * 1024 / 4) / 256, 256>>>(Wk, Wv, Wr, Wo, Wfc, Wmlp);
    // 1) RMS(x) -> fp16
    rms_kernel<<<M_ROWS / 8, 256>>>(x, p_normed);
    // 2) merged k|v|r GEMM (f32 outputs for the scan)
    gemm_h<4><<<gemmKVR, 256, SMEM_TOTAL>>>(p_normed, cWkvr, p_k, D_DIM, 3 * D_DIM, p_v, p_r);
    // 3) chunked RWKV scan, fuse r*wkv into g_a (fp16)
    scan_carry<<<dim3(D_DIM / 256, CH_C, B_SZ), 256>>>(p_k, p_v, td);
    scan_combine<<<dim3(D_DIM / 256, B_SZ), 256>>>(td);
    scan_apply<<<dim3(D_DIM / 256, CH_C, B_SZ), 256>>>(p_k, p_v, p_r, td, tfst);
    // 4) o-GEMM + residual -> x1 (f32)
    gemm_h<2><<<gemmD, 256, SMEM_TOTAL>>>(p_a, cWo, p_x1, D_DIM, D_DIM, x, mscl);
    // 5) RMS(x1) -> fp16
    rms_kernel<<<M_ROWS / 8, 256>>>(p_x1, p_normed);
    // 6) fc-GEMM with leaky(0.5)^2 epilogue -> h2 (fp16)
    gemm_h<3><<<gemmH, 256, SMEM_TOTAL>>>(p_normed, cWfc, p_h2, D_DIM, H_DIM, nullptr, nullptr);
    // 7) mlp-GEMM + residual -> out (f32)
    gemm_h<2><<<gemmD, 256, SMEM_TOTAL>>>(p_h2, cWmlp, out, H_DIM, D_DIM, p_x1, pscl);
}

// round 7
// speedup vs baseline: 1.8163x; 1.0177x over previous
#include <cuda_runtime.h>
#include <cuda_fp16.h>
#include <cstdint>

// ---------------------------------------------------------------------------
// HybridBlock: RMS -> merged{k,v,r} GEMM -> RWKV chunked scan -> o-GEMM(+res)
//              -> RMS -> fc-GEMM(leaky^2) -> mlp-GEMM(+res)
// GEMMs: mma.sync.m16n8k16 fp16 (fp32 accum), warp tile 64x64 (4 warps/CTA),
// cp.async 6-stage pipeline, 2 CTAs/SM.
// ---------------------------------------------------------------------------

#define S_LEN 4096
#define B_SZ  4
#define D_DIM 1024
#define H_DIM 4096
#define M_ROWS (B_SZ * S_LEN)      // 16384
#define CH_L  128
#define CH_C  (S_LEN / CH_L)       // 32

// Scratch (device globals: allocation-free per harness rules)
__device__ __half g_normed[(size_t)M_ROWS * D_DIM];
__device__ float  g_k[(size_t)M_ROWS * D_DIM];
__device__ float  g_v[(size_t)M_ROWS * D_DIM];
__device__ float  g_r[(size_t)M_ROWS * D_DIM];
__device__ __half g_a[(size_t)M_ROWS * D_DIM];
__device__ float  g_x1[(size_t)M_ROWS * D_DIM];
__device__ __half g_h2[(size_t)M_ROWS * H_DIM];
__device__ float  g_carry[CH_C * B_SZ * D_DIM];
__device__ float  g_entry[CH_C * B_SZ * D_DIM];
__device__ __half g_wh[(size_t)12 * 1024 * 1024];   // fp16 weights

__device__ __forceinline__ uint32_t smem_to_u32(const void* p) {
    uint32_t a;
    asm("{ .reg .u64 t; cvta.to.shared.u64 t, %1; cvt.u32.u64 %0, t; }"
        : "=r"(a) : "l"(p));
    return a;
}

#define CP_ASYNC16(dst, src) \
    asm volatile("cp.async.cg.shared.global [%0], [%1], 16;" \
                 :: "r"(dst), "l"(src) : "memory")
#define CP_COMMIT() asm volatile("cp.async.commit_group;" ::: "memory")
#define CP_WAIT4()  asm volatile("cp.async.wait_group 4;" ::: "memory")

#define LDS128(r0, r1, r2, r3, addr) \
    asm volatile("ld.shared.v4.b32 {%0,%1,%2,%3}, [%4];" \
                 : "=r"(r0), "=r"(r1), "=r"(r2), "=r"(r3) : "r"(addr))

#define MMA_F16(d, a0, a1, a2, a3, b0, b1) \
    asm volatile( \
        "mma.sync.aligned.m16n8k16.row.col.f32.f16.f16.f32 " \
        "{%0,%1,%2,%3}, {%4,%5,%6,%7}, {%8,%9}, {%0,%1,%2,%3};\n" \
        : "+f"((d)[0]), "+f"((d)[1]), "+f"((d)[2]), "+f"((d)[3]) \
        : "r"(a0), "r"(a1), "r"(a2), "r"(a3), "r"(b0), "r"(b1))

// ---------------------------------------------------------------------------
// Weight convert fp32 -> fp16, all 6 weights in one launch.
// g_wh layout: [Wk 1M][Wv 1M][Wr 1M][Wo 1M][Wfc 4M][Wmlp 4M] (floats count)
// ---------------------------------------------------------------------------
__global__ void cvt_all_kernel(const float* __restrict__ Wk, const float* __restrict__ Wv,
                               const float* __restrict__ Wr, const float* __restrict__ Wo,
                               const float* __restrict__ Wfc, const float* __restrict__ Wmlp) {
    const int M1 = 1024 * 1024 / 4;
    const size_t i = (size_t)blockIdx.x * 256 + threadIdx.x;  // float4 index
    const float* src;
    size_t li;
    if (i < 4 * M1) { src = (i < M1) ? Wk : (i < 2 * M1) ? Wv : (i < 3 * M1) ? Wr : Wo;
                      li = i & (M1 - 1); }
    else if (i < 8 * M1) { src = Wfc;  li = i - 4 * M1; }
    else                 { src = Wmlp; li = i - 8 * M1; }
    const float4 v = reinterpret_cast<const float4*>(src)[li];
    const __half2 h0 = __floats2half2_rn(v.x, v.y);
    const __half2 h1 = __floats2half2_rn(v.z, v.w);
    uint2 u;
    u.x = *reinterpret_cast<const uint32_t*>(&h0);
    u.y = *reinterpret_cast<const uint32_t*>(&h1);
    reinterpret_cast<uint2*>(g_wh)[i] = u;
}

// ---------------------------------------------------------------------------
// RMS norm: warp per row, output fp16.
// ---------------------------------------------------------------------------
__global__ void rms_kernel(const float* __restrict__ x, __half* __restrict__ out) {
    const int w = threadIdx.x >> 5, lid = threadIdx.x & 31;
    const int row = blockIdx.x * 8 + w;
    const float4* xr = reinterpret_cast<const float4*>(x + (size_t)row * D_DIM);
    float4 va[8];
    float ss = 0.f;
    #pragma unroll
    for (int i = 0; i < 8; i++) {
        va[i] = xr[lid + 32 * i];
        ss += va[i].x * va[i].x + va[i].y * va[i].y + va[i].z * va[i].z + va[i].w * va[i].w;
    }
    #pragma unroll
    for (int o = 16; o > 0; o >>= 1) ss += __shfl_xor_sync(0xffffffffu, ss, o);
    const float inv = rsqrtf(ss * (1.0f / (float)D_DIM) + 1e-6f);
    uint2* orow = reinterpret_cast<uint2*>(out + (size_t)row * D_DIM);
    #pragma unroll
    for (int i = 0; i < 8; i++) {
        const __half2 h0 = __floats2half2_rn(va[i].x * inv, va[i].y * inv);
        const __half2 h1 = __floats2half2_rn(va[i].z * inv, va[i].w * inv);
        uint2 u;
        u.x = *reinterpret_cast<const uint32_t*>(&h0);
        u.y = *reinterpret_cast<const uint32_t*>(&h1);
        orow[lid + 32 * i] = u;
    }
}

// ---------------------------------------------------------------------------
// RWKV chunked scan (fp32 exact factorization)
// ---------------------------------------------------------------------------
__global__ void scan_carry(const float* __restrict__ k, const float* __restrict__ v,
                           const float* __restrict__ td) {
    const int d = blockIdx.x * 256 + threadIdx.x;
    const int c = blockIdx.y, b = blockIdx.z;
    const float ew = expf(-expf(td[d]));
    size_t base = ((size_t)b * S_LEN + (size_t)c * CH_L) * D_DIM + d;
    float carry = 0.f;
    #pragma unroll 4
    for (int i = 0; i < CH_L; i++) {
        const float kv = k[base] * v[base];
        carry = ew * carry + kv;
        base += D_DIM;
    }
    g_carry[((size_t)c * B_SZ + b) * D_DIM + d] = carry;
}

__global__ void scan_combine(const float* __restrict__ td) {
    const int d = blockIdx.x * 256 + threadIdx.x;
    const int b = blockIdx.y;
    const float ewL = expf(-(float)CH_L * expf(td[d]));
    float s = 0.f;
    #pragma unroll
    for (int c = 0; c < CH_C; c++) {
        const size_t idx = ((size_t)c * B_SZ + b) * D_DIM + d;
        g_entry[idx] = s;
        s = ewL * s + g_carry[idx];
    }
}

__global__ void scan_apply(const float* __restrict__ k, const float* __restrict__ v,
                           const float* __restrict__ r,
                           const float* __restrict__ td, const float* __restrict__ tfirst) {
    const int d = blockIdx.x * 256 + threadIdx.x;
    const int c = blockIdx.y, b = blockIdx.z;
    const float ew = expf(-expf(td[d]));
    const float eu = expf(tfirst[d]);
    float s = g_entry[((size_t)c * B_SZ + b) * D_DIM + d];
    size_t base = ((size_t)b * S_LEN + (size_t)c * CH_L) * D_DIM + d;
    #pragma unroll 4
    for (int i = 0; i < CH_L; i++) {
        const float kv = k[base] * v[base];
        const float wkv = s + eu * kv;
        g_a[base] = __float2half_rn(r[base] * wkv);   // next GEMM A operand
        s = ew * s + kv;
        base += D_DIM;
    }
}

// ---------------------------------------------------------------------------
// fp16 mma.sync GEMM: C[M,N] = A[M,K] @ B[N,K]^T (A,B fp16, fp32 accum).
// Block 128x128xK32, 128 threads, 4 warps (2x2), warp tile 64x64.
// smem rows: 32 halfs (64B); one LDS.128 pair per A mi covers both k-steps,
// one LDS.128 per B ni covers both (shared logical-k bijection, exact).
// cp.async 6-stage ring (96KB), 2 CTAs/SM.
// EPI: 2=res+scale*acc (f32 out) 3=(leaky0.5)^2 (fp16 out) 4=merged-kvr (f32)
// ---------------------------------------------------------------------------
#define NST 6
#define STAGE_BYTES 16384    // A 8KB + B 8KB
#define SMEM_TOTAL (NST * STAGE_BYTES)

template <int EPI>
__global__ void __launch_bounds__(128, 2) gemm_h(
    const __half* __restrict__ A, const __half* __restrict__ Bw,
    void* __restrict__ Cout, int K, int N,
    const float* __restrict__ res, const float* __restrict__ scale)
{
    extern __shared__ char smem[];
    const uint32_t sb = smem_to_u32(smem);
    const int tid = threadIdx.x;
    const int bn = blockIdx.x, bm = blockIdx.y;
    const int warp = tid >> 5, lane = tid & 31;
    const int wm = warp >> 1, wn = warp & 1;      // 2x2 warp grid, 64x64 tiles
    const int gid = lane >> 2, tig = lane & 3;

    const __half* Ab = A + (size_t)bm * 128 * K;
    const __half* Bb = Bw + (size_t)bn * 128 * K;

    // cp.async: stage = 512 A-chunks + 512 B-chunks, 16B (8 halfs) each.
    // chunk i: row i>>2, k-offset (i&3)*8 halfs. 128 threads x 4 chunks each.
    const int i0 = tid, i1 = tid + 128, i2 = tid + 256, i3 = tid + 384;
    const __half* gA0 = Ab + (size_t)(i0 >> 2) * K + (i0 & 3) * 8;
    const __half* gA1 = Ab + (size_t)(i1 >> 2) * K + (i1 & 3) * 8;
    const __half* gA2 = Ab + (size_t)(i2 >> 2) * K + (i2 & 3) * 8;
    const __half* gA3 = Ab + (size_t)(i3 >> 2) * K + (i3 & 3) * 8;
    const __half* gB0 = Bb + (size_t)(i0 >> 2) * K + (i0 & 3) * 8;
    const __half* gB1 = Bb + (size_t)(i1 >> 2) * K + (i1 & 3) * 8;
    const __half* gB2 = Bb + (size_t)(i2 >> 2) * K + (i2 & 3) * 8;
    const __half* gB3 = Bb + (size_t)(i3 >> 2) * K + (i3 & 3) * 8;
    const uint32_t dA0 = sb + i0 * 16, dA1 = sb + i1 * 16;
    const uint32_t dA2 = sb + i2 * 16, dA3 = sb + i3 * 16;
    const uint32_t dB0 = sb + 8192 + i0 * 16, dB1 = sb + 8192 + i1 * 16;
    const uint32_t dB2 = sb + 8192 + i2 * 16, dB3 = sb + 8192 + i3 * 16;

    float acc[4][8][4];
    #pragma unroll
    for (int i = 0; i < 4; i++)
        #pragma unroll
        for (int j = 0; j < 8; j++)
            #pragma unroll
            for (int l = 0; l < 4; l++) acc[i][j][l] = 0.f;

    const int KT = K >> 5;     // 32 halfs per tile

    // prologue: stages 0..4
    #pragma unroll
    for (int s = 0; s < NST - 1; s++) {
        const uint32_t so = s * STAGE_BYTES;
        const int ko = s * 32;
        CP_ASYNC16(dA0 + so, gA0 + ko); CP_ASYNC16(dA1 + so, gA1 + ko);
        CP_ASYNC16(dA2 + so, gA2 + ko); CP_ASYNC16(dA3 + so, gA3 + ko);
        CP_ASYNC16(dB0 + so, gB0 + ko); CP_ASYNC16(dB1 + so, gB1 + ko);
        CP_ASYNC16(dB2 + so, gB2 + ko); CP_ASYNC16(dB3 + so, gB3 + ko);
        CP_COMMIT();
    }

    const uint32_t a_base = sb + (uint32_t)(wm * 64 + gid) * 64 + tig * 16;
    const uint32_t b_base = sb + 8192 + (uint32_t)(wn * 64 + gid) * 64 + tig * 16;

    int s_cur = 0, s_nxt = NST - 1;
    for (int kt = 0; kt < KT; kt++) {
        CP_WAIT4();
        __syncthreads();

        // prefetch stage s_nxt (its consumers finished last iteration)
        const int kn = kt + NST - 1;
        if (kn < KT) {
            const uint32_t sn = (uint32_t)s_nxt * STAGE_BYTES;
            const int ko = kn * 32;
            CP_ASYNC16(dA0 + sn, gA0 + ko); CP_ASYNC16(dA1 + sn, gA1 + ko);
            CP_ASYNC16(dA2 + sn, gA2 + ko); CP_ASYNC16(dA3 + sn, gA3 + ko);
            CP_ASYNC16(dB0 + sn, gB0 + ko); CP_ASYNC16(dB1 + sn, gB1 + ko);
            CP_ASYNC16(dB2 + sn, gB2 + ko); CP_ASYNC16(dB3 + sn, gB3 + ko);
        }
        CP_COMMIT();

        const uint32_t so = (uint32_t)s_cur * STAGE_BYTES;
        uint32_t bf[8][4];
        #pragma unroll
        for (int ni = 0; ni < 8; ni++)
            LDS128(bf[ni][0], bf[ni][1], bf[ni][2], bf[ni][3], b_base + so + ni * 512);

        #pragma unroll
        for (int mi = 0; mi < 4; mi++) {
            uint32_t lo0, lo1, lo2, lo3, hi0, hi1, hi2, hi3;
            LDS128(lo0, lo1, lo2, lo3, a_base + so + mi * 1024);
            LDS128(hi0, hi1, hi2, hi3, a_base + so + mi * 1024 + 512);
            #pragma unroll
            for (int ni = 0; ni < 8; ni++) {
                MMA_F16(acc[mi][ni], lo0, hi0, lo1, hi1, bf[ni][0], bf[ni][1]);  // k-step 0
                MMA_F16(acc[mi][ni], lo2, hi2, lo3, hi3, bf[ni][2], bf[ni][3]);  // k-step 1
            }
        }

        if (++s_cur == NST) s_cur = 0;
        if (++s_nxt == NST) s_nxt = 0;
    }

    // epilogue
    float* Cf = (float*)Cout;
    __half* Ch = (__half*)Cout;
    int seg = 0, Nout = N, col_base = bn * 128;
    if (EPI == 4) {
        seg = bn >> 3;
        Cf = (seg == 0) ? (float*)Cout : (seg == 1) ? (float*)res : (float*)scale;
        Nout = D_DIM;
        col_base = (bn & 7) * 128;
    }
    const int row0 = bm * 128 + wm * 64 + gid;
    const int col0 = col_base + wn * 64 + 2 * tig;
    #pragma unroll
    for (int mi = 0; mi < 4; mi++) {
        #pragma unroll
        for (int ni = 0; ni < 8; ni++) {
            const int gc = col0 + ni * 8;
            #pragma unroll
            for (int h = 0; h < 2; h++) {
                const int gr = row0 + mi * 16 + h * 8;
                float v0 = acc[mi][ni][2 * h + 0];
                float v1 = acc[mi][ni][2 * h + 1];
                if (EPI == 2) {
                    const float2 rr = *reinterpret_cast<const float2*>(res + (size_t)gr * N + gc);
                    const float2 sc = *reinterpret_cast<const float2*>(scale + gc);
                    *reinterpret_cast<float2*>(Cf + (size_t)gr * N + gc) =
                        make_float2(rr.x + sc.x * v0, rr.y + sc.y * v1);
                } else if (EPI == 3) {
                    const float t0 = v0 > 0.f ? v0 : 0.5f * v0;
                    const float t1 = v1 > 0.f ? v1 : 0.5f * v1;
                    const __half2 hv = __floats2half2_rn(t0 * t0, t1 * t1);
                    *reinterpret_cast<__half2*>(Ch + (size_t)gr * N + gc) = hv;
                } else if (EPI == 4) {
                    if (seg == 2) {
                        v0 = 1.f / (1.f + expf(-v0));
                        v1 = 1.f / (1.f + expf(-v1));
                    }
                    *reinterpret_cast<float2*>(Cf + (size_t)gr * Nout + gc) =
                        make_float2(v0, v1);
                }
            }
        }
    }
}

// ---------------------------------------------------------------------------
// Launch
// ---------------------------------------------------------------------------
extern "C" void kernel_launch(void* const* d_in, const int* in_sizes, int n_in,
                              void* d_out, int out_size) {
    const float* x     = (const float*)d_in[0];
    const float* Wk    = (const float*)d_in[1];
    const float* Wv    = (const float*)d_in[2];
    const float* Wr    = (const float*)d_in[3];
    const float* Wo    = (const float*)d_in[4];
    const float* td    = (const float*)d_in[5];
    const float* tfst  = (const float*)d_in[6];
    const float* mscl  = (const float*)d_in[7];
    const float* Wfc   = (const float*)d_in[8];
    const float* Wmlp  = (const float*)d_in[9];
    const float* pscl  = (const float*)d_in[10];
    float* out = (float*)d_out;

    float *p_k, *p_v, *p_r, *p_x1;
    __half *p_normed, *p_a, *p_h2, *p_w;
    cudaGetSymbolAddress((void**)&p_normed, g_normed);
    cudaGetSymbolAddress((void**)&p_k, g_k);
    cudaGetSymbolAddress((void**)&p_v, g_v);
    cudaGetSymbolAddress((void**)&p_r, g_r);
    cudaGetSymbolAddress((void**)&p_a, g_a);
    cudaGetSymbolAddress((void**)&p_x1, g_x1);
    cudaGetSymbolAddress((void**)&p_h2, g_h2);
    cudaGetSymbolAddress((void**)&p_w, g_wh);

    __half* cWkvr = p_w;                                  // [3072,1024]
    __half* cWo   = p_w + (size_t)3 * 1024 * 1024;
    __half* cWfc  = p_w + (size_t)4 * 1024 * 1024;
    __half* cWmlp = p_w + (size_t)8 * 1024 * 1024;

    cudaFuncSetAttribute(gemm_h<2>, cudaFuncAttributeMaxDynamicSharedMemorySize, SMEM_TOTAL);
    cudaFuncSetAttribute(gemm_h<3>, cudaFuncAttributeMaxDynamicSharedMemorySize, SMEM_TOTAL);
    cudaFuncSetAttribute(gemm_h<4>, cudaFuncAttributeMaxDynamicSharedMemorySize, SMEM_TOTAL);

    const dim3 gemmD(D_DIM / 128, M_ROWS / 128);        // (8, 128)
    const dim3 gemmKVR(3 * D_DIM / 128, M_ROWS / 128);  // (24, 128)
    const dim3 gemmH(H_DIM / 128, M_ROWS / 128);        // (32, 128)

    // 0) weights -> fp16 (one launch)
    cvt_all_kernel<<<(12 * 1024 * 1024 / 4) / 256, 256>>>(Wk, Wv, Wr, Wo, Wfc, Wmlp);
    // 1) RMS(x) -> fp16
    rms_kernel<<<M_ROWS / 8, 256>>>(x, p_normed);
    // 2) merged k|v|r GEMM (f32 outputs for the scan)
    gemm_h<4><<<gemmKVR, 128, SMEM_TOTAL>>>(p_normed, cWkvr, p_k, D_DIM, 3 * D_DIM, p_v, p_r);
    // 3) chunked RWKV scan, fuse r*wkv into g_a (fp16)
    scan_carry<<<dim3(D_DIM / 256, CH_C, B_SZ), 256>>>(p_k, p_v, td);
    scan_combine<<<dim3(D_DIM / 256, B_SZ), 256>>>(td);
    scan_apply<<<dim3(D_DIM / 256, CH_C, B_SZ), 256>>>(p_k, p_v, p_r, td, tfst);
    // 4) o-GEMM + residual -> x1 (f32)
    gemm_h<2><<<gemmD, 128, SMEM_TOTAL>>>(p_a, cWo, p_x1, D_DIM, D_DIM, x, mscl);
    // 5) RMS(x1) -> fp16
    rms_kernel<<<M_ROWS / 8, 256>>>(p_x1, p_normed);
    // 6) fc-GEMM with leaky(0.5)^2 epilogue -> h2 (fp16)
    gemm_h<3><<<gemmH, 128, SMEM_TOTAL>>>(p_normed, cWfc, p_h2, D_DIM, H_DIM, nullptr, nullptr);
    // 7) mlp-GEMM + residual -> out (f32)
    gemm_h<2><<<gemmD, 128, SMEM_TOTAL>>>(p_h2, cWmlp, out, H_DIM, D_DIM, p_x1, pscl);
}